// round 1
// baseline (speedup 1.0000x reference)
#include <cuda_runtime.h>
#include <math.h>

#define TM 128      // tokens per CTA
#define TN 128      // 2*E combined output columns (router | noise)
#define KC 32       // K chunk
#define NEXP 64     // experts
#define DDIM 2048   // hidden dim
#define NTHREADS 256
#define XS 36       // smem tile row stride (floats), conflict-free
#define AS 133      // acc staging row stride (floats), conflict-free column reads
#define US 65       // u staging row stride (floats)

// smem budget (floats):
//  phase1: sx[2][128][36] + sw[2][128][36] = 18432
//  phase2: acc[128][133] (17024) + su[128][65] (8320) = 25344  -> 101376 bytes
#define SMEM_FLOATS 25344
#define SMEM_BYTES  (SMEM_FLOATS * 4)

extern __shared__ float smem[];

__global__ __launch_bounds__(NTHREADS, 1)
void topk_router_kernel(const float* __restrict__ x,
                        const float* __restrict__ rw,
                        const float* __restrict__ rb,
                        const float* __restrict__ nw,
                        const float* __restrict__ nb,
                        const float* __restrict__ u,
                        float* __restrict__ out,
                        int M)
{
    float* sx = smem;                 // [2][TM][XS]
    float* sw = smem + 2 * TM * XS;   // [2][TM][XS]
    float* acc_s = smem;              // reused after GEMM: [TM][AS]
    float* su = smem + TM * AS;       // [TM][US]

    const int tid = threadIdx.x;
    const int tx = tid & 15;
    const int ty = tid >> 4;
    const int m0 = blockIdx.x * TM;

    float acc[8][8];
#pragma unroll
    for (int i = 0; i < 8; i++)
#pragma unroll
        for (int j = 0; j < 8; j++) acc[i][j] = 0.f;

    const int NK = DDIM / KC;  // 64

    // ---- preload tile 0 into buffer 0 ----
    {
        const float* xg = x + (size_t)m0 * DDIM;
#pragma unroll
        for (int t = 0; t < 4; t++) {
            int q = tid + t * NTHREADS;
            int r = q >> 3, c = q & 7;
            float4 v = *(const float4*)(xg + (size_t)r * DDIM + c * 4);
            *(float4*)(sx + r * XS + c * 4) = v;
        }
#pragma unroll
        for (int t = 0; t < 4; t++) {
            int q = tid + t * NTHREADS;
            int r = q >> 3, c = q & 7;
            const float* wg = (r < NEXP) ? (rw + (size_t)r * DDIM)
                                         : (nw + (size_t)(r - NEXP) * DDIM);
            float4 v = *(const float4*)(wg + c * 4);
            *(float4*)(sw + r * XS + c * 4) = v;
        }
    }
    __syncthreads();

    // ---- main K loop, double buffered ----
    for (int kt = 0; kt < NK; kt++) {
        const int buf = kt & 1;
        float* cx = sx + buf * TM * XS;
        float* cw = sw + buf * TM * XS;

        if (kt + 1 < NK) {
            const int kk = (kt + 1) * KC;
            float* px = sx + (buf ^ 1) * TM * XS;
            float* pw = sw + (buf ^ 1) * TM * XS;
            const float* xg = x + (size_t)m0 * DDIM + kk;
#pragma unroll
            for (int t = 0; t < 4; t++) {
                int q = tid + t * NTHREADS;
                int r = q >> 3, c = q & 7;
                float4 v = *(const float4*)(xg + (size_t)r * DDIM + c * 4);
                *(float4*)(px + r * XS + c * 4) = v;
            }
#pragma unroll
            for (int t = 0; t < 4; t++) {
                int q = tid + t * NTHREADS;
                int r = q >> 3, c = q & 7;
                const float* wg = ((r < NEXP) ? (rw + (size_t)r * DDIM)
                                              : (nw + (size_t)(r - NEXP) * DDIM)) + kk;
                float4 v = *(const float4*)(wg + c * 4);
                *(float4*)(pw + r * XS + c * 4) = v;
            }
        }

        // compute on current buffer: fragments m = ty + 16*i, n = tx + 16*j
#pragma unroll
        for (int kq = 0; kq < KC / 4; kq++) {
            float a[8][4], b[8][4];
#pragma unroll
            for (int i = 0; i < 8; i++) {
                float4 v = *(float4*)(cx + (ty + 16 * i) * XS + kq * 4);
                a[i][0] = v.x; a[i][1] = v.y; a[i][2] = v.z; a[i][3] = v.w;
            }
#pragma unroll
            for (int j = 0; j < 8; j++) {
                float4 v = *(float4*)(cw + (tx + 16 * j) * XS + kq * 4);
                b[j][0] = v.x; b[j][1] = v.y; b[j][2] = v.z; b[j][3] = v.w;
            }
#pragma unroll
            for (int k = 0; k < 4; k++)
#pragma unroll
                for (int i = 0; i < 8; i++)
#pragma unroll
                    for (int j = 0; j < 8; j++)
                        acc[i][j] += a[i][k] * b[j][k];
        }
        __syncthreads();
    }

    // ---- stage accumulators to smem (reuses tile buffers, safe post-sync) ----
#pragma unroll
    for (int i = 0; i < 8; i++)
#pragma unroll
        for (int j = 0; j < 8; j++)
            acc_s[(ty + 16 * i) * AS + (tx + 16 * j)] = acc[i][j];

    // cooperative coalesced load of noise_u tile into smem [TM][US]
    {
        const float* ug = u + (size_t)m0 * NEXP;
        for (int q = tid; q < TM * NEXP; q += NTHREADS) {
            int r = q >> 6, c = q & 63;
            su[r * US + c] = ug[(size_t)r * NEXP + c];
        }
    }
    __syncthreads();

    // ---- per-token epilogue: noisy logits, top-2, sparse softmax ----
    if (tid < TM) {
        const int m = m0 + tid;
        float* row = acc_s + tid * AS;
        const float* urow = su + tid * US;

        float v1 = -INFINITY, v2 = -INFINITY;
        int i1 = 0, i2 = 0;
        for (int e = 0; e < NEXP; e++) {
            float lg = row[e] + rb[e];
            float nz = row[NEXP + e] + nb[e];
            // softplus = max(x,0) + log1p(exp(-|x|))  (matches jax.nn.softplus)
            float sp = fmaxf(nz, 0.f) + log1pf(expf(-fabsf(nz)));
            float nv = lg + sp * urow[e];
            if (nv > v1) { v2 = v1; i2 = i1; v1 = nv; i1 = e; }
            else if (nv > v2) { v2 = nv; i2 = e; }
        }
        float e2 = expf(v2 - v1);
        float den = 1.f + e2;
        float p1 = 1.f / den;
        float p2 = e2 / den;

        // overwrite staging row with output probabilities (mostly zeros)
        for (int e = 0; e < NEXP; e++) row[e] = 0.f;
        row[i1] = p1;
        row[i2] = p2;

        // indices appended after the [M, NEXP] prob block, as float values
        float* oid = out + (size_t)M * NEXP;
        oid[(size_t)m * 2 + 0] = (float)i1;
        oid[(size_t)m * 2 + 1] = (float)i2;
    }
    __syncthreads();

    // ---- coalesced write of probabilities ----
    for (int t = tid; t < TM * (NEXP / 4); t += NTHREADS) {
        int r = t >> 4;            // token within tile
        int c4 = (t & 15) * 4;     // column quad
        float4 v = make_float4(acc_s[r * AS + c4 + 0],
                               acc_s[r * AS + c4 + 1],
                               acc_s[r * AS + c4 + 2],
                               acc_s[r * AS + c4 + 3]);
        *(float4*)(out + (size_t)(m0 + r) * NEXP + c4) = v;
    }
}

extern "C" void kernel_launch(void* const* d_in, const int* in_sizes, int n_in,
                              void* d_out, int out_size)
{
    const float* x  = (const float*)d_in[0];
    const float* rw = (const float*)d_in[1];
    const float* rb = (const float*)d_in[2];
    const float* nw = (const float*)d_in[3];
    const float* nb = (const float*)d_in[4];
    const float* u  = (const float*)d_in[5];
    // d_in[6] = top_k (assumed 2)

    const int M = in_sizes[0] / DDIM;  // 16384 tokens

    static bool attr_set = false;
    if (!attr_set) {
        cudaFuncSetAttribute(topk_router_kernel,
                             cudaFuncAttributeMaxDynamicSharedMemorySize,
                             SMEM_BYTES);
        attr_set = true;
    }

    dim3 grid(M / TM);
    topk_router_kernel<<<grid, NTHREADS, SMEM_BYTES>>>(x, rw, rb, nw, nb, u,
                                                       (float*)d_out, M);
}

// round 3
// speedup vs baseline: 1.4738x; 1.4738x over previous
#include <cuda_runtime.h>
#include <cuda_bf16.h>
#include <math.h>
#include <stdint.h>

#define DDIM   2048
#define NEXP   64
#define NCOL   128            // router(64) | noise(64) output columns
#define TM     128            // tokens per CTA
#define KC     32             // K elems per chunk
#define NC     (DDIM / KC)    // 64 chunks
#define NTHREADS 256
#define AS     133            // epilogue staging row stride (floats)
#define US     65

#define RSTRIDE 80            // smem row stride in bytes (40 bf16) -> conflict-free ldmatrix
#define APL    (128 * RSTRIDE)        // 10240 B per plane (128 rows)
#define ABUF   (3 * APL)              // 30720 B per buffer (3 planes)
#define SM_A   0
#define SM_B   (2 * ABUF)             // 61440
#define SMEM_BYTES (4 * ABUF)         // 122880

// pre-split W planes (router rows 0..63, noise rows 64..127)
__device__ __nv_bfloat16 g_wp[3][NCOL][DDIM];

// ---------------- helpers ----------------
__device__ __forceinline__ uint32_t smem_u32(const void* p) {
    uint32_t a;
    asm("{ .reg .u64 t; cvta.to.shared.u64 t, %1; cvt.u32.u64 %0, t; }" : "=r"(a) : "l"(p));
    return a;
}
__device__ __forceinline__ uint32_t pack2(float lo, float hi) {
    uint32_t r;
    asm("cvt.rn.bf16x2.f32 %0, %1, %2;" : "=r"(r) : "f"(hi), "f"(lo));
    return r;
}
// 3-way bf16 split of a float pair (lo,hi) -> 3 bf16x2 regs
__device__ __forceinline__ void split2(float lo, float hi,
                                       uint32_t& u0, uint32_t& u1, uint32_t& u2) {
    u0 = pack2(lo, hi);
    float l0 = __uint_as_float(u0 << 16);
    float h0 = __uint_as_float(u0 & 0xffff0000u);
    float rl = lo - l0, rh = hi - h0;
    u1 = pack2(rl, rh);
    float l1 = __uint_as_float(u1 << 16);
    float h1 = __uint_as_float(u1 & 0xffff0000u);
    u2 = pack2(rl - l1, rh - h1);
}
#define LDSM4(r, a) \
    asm volatile("ldmatrix.sync.aligned.m8n8.x4.shared.b16 {%0,%1,%2,%3}, [%4];" \
        : "=r"((r)[0]), "=r"((r)[1]), "=r"((r)[2]), "=r"((r)[3]) : "r"(a))
#define LDSM2(r, a) \
    asm volatile("ldmatrix.sync.aligned.m8n8.x2.shared.b16 {%0,%1}, [%2];" \
        : "=r"((r)[0]), "=r"((r)[1]) : "r"(a))
#define MMA16816(d, a, b) \
    asm volatile("mma.sync.aligned.m16n8k16.row.col.f32.bf16.bf16.f32 " \
        "{%0,%1,%2,%3}, {%4,%5,%6,%7}, {%8,%9}, {%0,%1,%2,%3};" \
        : "+f"((d)[0]), "+f"((d)[1]), "+f"((d)[2]), "+f"((d)[3]) \
        : "r"((a)[0]), "r"((a)[1]), "r"((a)[2]), "r"((a)[3]), "r"((b)[0]), "r"((b)[1]))

// ---------------- prep: split W into 3 bf16 planes ----------------
__global__ void prep_w_kernel(const float* __restrict__ rw, const float* __restrict__ nw) {
    int idx = blockIdx.x * blockDim.x + threadIdx.x;   // 0 .. 128*2048-1
    int r = idx >> 11, k = idx & 2047;
    float v = (r < NEXP) ? rw[r * DDIM + k] : nw[(r - NEXP) * DDIM + k];
    __nv_bfloat16 b0 = __float2bfloat16_rn(v);
    float f0 = __bfloat162float(b0);
    float r1 = v - f0;
    __nv_bfloat16 b1 = __float2bfloat16_rn(r1);
    float f1 = __bfloat162float(b1);
    __nv_bfloat16 b2 = __float2bfloat16_rn(r1 - f1);
    g_wp[0][r][k] = b0;
    g_wp[1][r][k] = b1;
    g_wp[2][r][k] = b2;
}

// ---------------- main fused kernel ----------------
extern __shared__ char smem[];

__global__ __launch_bounds__(NTHREADS, 1)
void router_hmma_kernel(const float* __restrict__ x,
                        const float* __restrict__ rb,
                        const float* __restrict__ nb,
                        const float* __restrict__ u,
                        float* __restrict__ out,
                        int M)
{
    const int tid  = threadIdx.x;
    const int wid  = tid >> 5;
    const int lane = tid & 31;
    const int wm   = wid >> 2;     // 0..1  -> 64-row slab
    const int wn   = wid & 3;      // 0..3  -> 32-col slab
    const int m0   = blockIdx.x * TM;
    const uint32_t sb = smem_u32(smem);

    // per-lane ldmatrix byte offsets (within a plane)
    uint32_t aoff[4], boff[4];
#pragma unroll
    for (int mt = 0; mt < 4; mt++) {
        int row = wm * 64 + mt * 16 + (lane & 7) + 8 * ((lane >> 3) & 1);
        aoff[mt] = (uint32_t)(row * RSTRIDE + 16 * ((lane >> 4) & 1));
    }
#pragma unroll
    for (int nt = 0; nt < 4; nt++) {
        int l = lane & 15;
        int row = wn * 32 + nt * 8 + (l & 7);
        boff[nt] = (uint32_t)(row * RSTRIDE + 16 * ((l >> 3) & 1));
    }

    float acc[4][4][4];
#pragma unroll
    for (int mt = 0; mt < 4; mt++)
#pragma unroll
        for (int nt = 0; nt < 4; nt++)
#pragma unroll
            for (int e = 0; e < 4; e++) acc[mt][nt][e] = 0.f;

    float4 av[4];
    uint4  bv[6];

    // global-load lambdas (manual)
#define LOAD_A(c)  {                                                      \
    _Pragma("unroll")                                                     \
    for (int i = 0; i < 4; i++) {                                         \
        int f = tid + i * NTHREADS;                                       \
        int row = f >> 3, kq = f & 7;                                     \
        av[i] = *(const float4*)(x + (size_t)(m0 + row) * DDIM + (c) * KC + kq * 4); } }
#define LOAD_B(c)  {                                                      \
    _Pragma("unroll")                                                     \
    for (int i = 0; i < 6; i++) {                                         \
        int q = tid + i * NTHREADS;                                       \
        int pl = q >> 9, rem = q & 511, row = rem >> 2, kq = rem & 3;     \
        bv[i] = *(const uint4*)&g_wp[pl][row][(c) * KC + kq * 8]; } }
#define STORE_AB(buf) {                                                   \
    _Pragma("unroll")                                                     \
    for (int i = 0; i < 4; i++) {                                         \
        int f = tid + i * NTHREADS;                                       \
        int row = f >> 3, kq = f & 7;                                     \
        uint32_t p0a, p1a, p2a, p0b, p1b, p2b;                            \
        split2(av[i].x, av[i].y, p0a, p1a, p2a);                          \
        split2(av[i].z, av[i].w, p0b, p1b, p2b);                          \
        char* base = smem + SM_A + (buf) * ABUF + row * RSTRIDE + kq * 8; \
        *(uint2*)(base + 0 * APL) = make_uint2(p0a, p0b);                 \
        *(uint2*)(base + 1 * APL) = make_uint2(p1a, p1b);                 \
        *(uint2*)(base + 2 * APL) = make_uint2(p2a, p2b); }               \
    _Pragma("unroll")                                                     \
    for (int i = 0; i < 6; i++) {                                         \
        int q = tid + i * NTHREADS;                                       \
        int pl = q >> 9, rem = q & 511, row = rem >> 2, kq = rem & 3;     \
        *(uint4*)(smem + SM_B + (buf) * ABUF + pl * APL + row * RSTRIDE + kq * 16) = bv[i]; } }

    // prologue: chunk 0 -> buffer 0
    LOAD_A(0); LOAD_B(0);
    STORE_AB(0);
    __syncthreads();

    for (int c = 0; c < NC; c++) {
        const int buf = c & 1;
        if (c + 1 < NC) { LOAD_A(c + 1); LOAD_B(c + 1); }

        // ---- compute on current buffer: 2 k16-steps, 6 plane combos ----
#pragma unroll
        for (int ks = 0; ks < 2; ks++) {
            uint32_t a[3][4][4], b[3][4][2];
            const uint32_t abase = sb + SM_A + buf * ABUF + ks * 32;
            const uint32_t bbase = sb + SM_B + buf * ABUF + ks * 32;
#pragma unroll
            for (int pl = 0; pl < 3; pl++)
#pragma unroll
                for (int mt = 0; mt < 4; mt++)
                    LDSM4(a[pl][mt], abase + pl * APL + aoff[mt]);
#pragma unroll
            for (int pl = 0; pl < 3; pl++)
#pragma unroll
                for (int nt = 0; nt < 4; nt++)
                    LDSM2(b[pl][nt], bbase + pl * APL + boff[nt]);

            const int CA[6] = {0, 0, 1, 1, 0, 2};
            const int CB[6] = {0, 1, 0, 1, 2, 0};
#pragma unroll
            for (int q = 0; q < 6; q++)
#pragma unroll
                for (int mt = 0; mt < 4; mt++)
#pragma unroll
                    for (int nt = 0; nt < 4; nt++)
                        MMA16816(acc[mt][nt], a[CA[q]][mt], b[CB[q]][nt]);
        }

        if (c + 1 < NC) STORE_AB(buf ^ 1);
        __syncthreads();
    }

    // ---- stage accumulators to smem (reuses tile region) ----
    float* acc_s = (float*)smem;            // [TM][AS]
    float* su    = acc_s + TM * AS;         // [TM][US]
#pragma unroll
    for (int mt = 0; mt < 4; mt++)
#pragma unroll
        for (int nt = 0; nt < 4; nt++) {
            int r   = wm * 64 + mt * 16 + (lane >> 2);
            int col = wn * 32 + nt * 8 + (lane & 3) * 2;
            acc_s[r * AS + col]           = acc[mt][nt][0];
            acc_s[r * AS + col + 1]       = acc[mt][nt][1];
            acc_s[(r + 8) * AS + col]     = acc[mt][nt][2];
            acc_s[(r + 8) * AS + col + 1] = acc[mt][nt][3];
        }
    // noise_u tile
    {
        const float* ug = u + (size_t)m0 * NEXP;
        for (int q = tid; q < TM * NEXP; q += NTHREADS) {
            int r = q >> 6, cn = q & 63;
            su[r * US + cn] = ug[(size_t)r * NEXP + cn];
        }
    }
    __syncthreads();

    // ---- per-token epilogue: noisy logits, top-2, sparse softmax ----
    if (tid < TM) {
        const int m = m0 + tid;
        float* row = acc_s + tid * AS;
        const float* urow = su + tid * US;

        float v1 = -INFINITY, v2 = -INFINITY;
        int i1 = 0, i2 = 0;
        for (int e = 0; e < NEXP; e++) {
            float lg = row[e] + rb[e];
            float nz = row[NEXP + e] + nb[e];
            float sp = fmaxf(nz, 0.f) + log1pf(expf(-fabsf(nz)));
            float nv = lg + sp * urow[e];
            if (nv > v1) { v2 = v1; i2 = i1; v1 = nv; i1 = e; }
            else if (nv > v2) { v2 = nv; i2 = e; }
        }
        float e2 = expf(v2 - v1);
        float den = 1.f + e2;
        float p1 = 1.f / den;
        float p2 = e2 / den;

        for (int e = 0; e < NEXP; e++) row[e] = 0.f;
        row[i1] = p1;
        row[i2] = p2;

        float* oid = out + (size_t)M * NEXP;
        oid[(size_t)m * 2 + 0] = (float)i1;
        oid[(size_t)m * 2 + 1] = (float)i2;
    }
    __syncthreads();

    // coalesced probability writeback
    for (int t = tid; t < TM * (NEXP / 4); t += NTHREADS) {
        int r = t >> 4;
        int c4 = (t & 15) * 4;
        float4 v = make_float4(acc_s[r * AS + c4 + 0],
                               acc_s[r * AS + c4 + 1],
                               acc_s[r * AS + c4 + 2],
                               acc_s[r * AS + c4 + 3]);
        *(float4*)(out + (size_t)(m0 + r) * NEXP + c4) = v;
    }
}

extern "C" void kernel_launch(void* const* d_in, const int* in_sizes, int n_in,
                              void* d_out, int out_size)
{
    const float* x  = (const float*)d_in[0];
    const float* rw = (const float*)d_in[1];
    const float* rb = (const float*)d_in[2];
    const float* nw = (const float*)d_in[3];
    const float* nb = (const float*)d_in[4];
    const float* u  = (const float*)d_in[5];

    const int M = in_sizes[0] / DDIM;  // 16384

    static bool attr_set = false;
    if (!attr_set) {
        cudaFuncSetAttribute(router_hmma_kernel,
                             cudaFuncAttributeMaxDynamicSharedMemorySize,
                             SMEM_BYTES);
        attr_set = true;
    }

    prep_w_kernel<<<(NCOL * DDIM) / 256, 256>>>(rw, nw);
    router_hmma_kernel<<<M / TM, NTHREADS, SMEM_BYTES>>>(x, rb, nb, u, (float*)d_out, M);
}

// round 4
// speedup vs baseline: 2.5132x; 1.7053x over previous
#include <cuda_runtime.h>
#include <cuda_fp16.h>
#include <math.h>
#include <stdint.h>

#define DDIM   2048
#define NEXP   64
#define NCOL   128            // router(64) | noise(64) output columns
#define TM     128            // tokens per CTA
#define KC     64             // K elems per chunk
#define NC     (DDIM / KC)    // 32 chunks
#define NTHREADS 256
#define AS     133            // epilogue staging row stride (floats)
#define US     65
#define WSCALE 2048.0f
#define INVSCALE (1.0f / 2048.0f)

#define RSTRIDE 144           // smem row stride bytes (64 fp16 = 128B data + 16B pad)
#define APL    (128 * RSTRIDE)        // 18432 B per plane
#define ABUF   (2 * APL)              // 36864 B per buffer (2 planes)
#define SM_A   0
#define SM_B   (2 * ABUF)             // 73728
#define SMEM_BYTES (4 * ABUF)         // 147456

// pre-split W planes, scaled by 2048 (router rows 0..63, noise rows 64..127)
__device__ __half g_wp[2][NCOL][DDIM];

// ---------------- helpers ----------------
__device__ __forceinline__ uint32_t smem_u32(const void* p) {
    uint32_t a;
    asm("{ .reg .u64 t; cvta.to.shared.u64 t, %1; cvt.u32.u64 %0, t; }" : "=r"(a) : "l"(p));
    return a;
}
// 2-way fp16 split of a float pair (lo,hi) -> 2 f16x2 regs
__device__ __forceinline__ void split2(float lo, float hi, uint32_t& u0, uint32_t& u1) {
    __half2 h0 = __floats2half2_rn(lo, hi);           // .x=lo(low16), .y=hi(high16)
    float l0 = __half2float(__low2half(h0));
    float hh = __half2float(__high2half(h0));
    __half2 h1 = __floats2half2_rn(lo - l0, hi - hh);
    u0 = *reinterpret_cast<uint32_t*>(&h0);
    u1 = *reinterpret_cast<uint32_t*>(&h1);
}
#define LDSM4(r, a) \
    asm volatile("ldmatrix.sync.aligned.m8n8.x4.shared.b16 {%0,%1,%2,%3}, [%4];" \
        : "=r"((r)[0]), "=r"((r)[1]), "=r"((r)[2]), "=r"((r)[3]) : "r"(a))
#define LDSM2(r, a) \
    asm volatile("ldmatrix.sync.aligned.m8n8.x2.shared.b16 {%0,%1}, [%2];" \
        : "=r"((r)[0]), "=r"((r)[1]) : "r"(a))
#define MMA16816(d, a, b) \
    asm volatile("mma.sync.aligned.m16n8k16.row.col.f32.f16.f16.f32 " \
        "{%0,%1,%2,%3}, {%4,%5,%6,%7}, {%8,%9}, {%0,%1,%2,%3};" \
        : "+f"((d)[0]), "+f"((d)[1]), "+f"((d)[2]), "+f"((d)[3]) \
        : "r"((a)[0]), "r"((a)[1]), "r"((a)[2]), "r"((a)[3]), "r"((b)[0]), "r"((b)[1]))
#define CPASYNC16(dst, src) \
    asm volatile("cp.async.cg.shared.global [%0], [%1], 16;" :: "r"(dst), "l"(src) : "memory")

// ---------------- prep: split W into 2 scaled fp16 planes ----------------
__global__ void prep_w_kernel(const float* __restrict__ rw, const float* __restrict__ nw) {
    int idx = blockIdx.x * blockDim.x + threadIdx.x;   // 0 .. 128*2048-1
    int r = idx >> 11, k = idx & 2047;
    float v = WSCALE * ((r < NEXP) ? rw[r * DDIM + k] : nw[(r - NEXP) * DDIM + k]);
    __half b0 = __float2half_rn(v);
    float f0 = __half2float(b0);
    __half b1 = __float2half_rn(v - f0);
    g_wp[0][r][k] = b0;
    g_wp[1][r][k] = b1;
}

// ---------------- main fused kernel ----------------
extern __shared__ char smem[];

__global__ __launch_bounds__(NTHREADS, 1)
void router_hmma_kernel(const float* __restrict__ x,
                        const float* __restrict__ rb,
                        const float* __restrict__ nb,
                        const float* __restrict__ u,
                        float* __restrict__ out,
                        int M)
{
    const int tid  = threadIdx.x;
    const int wid  = tid >> 5;
    const int lane = tid & 31;
    const int wm   = wid >> 2;     // 0..1  -> 64-row slab
    const int wn   = wid & 3;      // 0..3  -> 32-col slab
    const int m0   = blockIdx.x * TM;
    const uint32_t sb = smem_u32(smem);

    // per-lane ldmatrix byte offsets (within a plane)
    uint32_t aoff[4], boff[4];
#pragma unroll
    for (int mt = 0; mt < 4; mt++) {
        int row = wm * 64 + mt * 16 + (lane & 7) + 8 * ((lane >> 3) & 1);
        aoff[mt] = (uint32_t)(row * RSTRIDE + 16 * ((lane >> 4) & 1));
    }
#pragma unroll
    for (int nt = 0; nt < 4; nt++) {
        int l = lane & 15;
        int row = wn * 32 + nt * 8 + (l & 7);
        boff[nt] = (uint32_t)(row * RSTRIDE + 16 * ((l >> 3) & 1));
    }

    float acc[4][4][4];
#pragma unroll
    for (int mt = 0; mt < 4; mt++)
#pragma unroll
        for (int nt = 0; nt < 4; nt++)
#pragma unroll
            for (int e = 0; e < 4; e++) acc[mt][nt][e] = 0.f;

    float4 av[8];

    // A: 128 rows x 64 floats per chunk -> 8 float4 per thread
#define LOAD_A(c)  {                                                          \
    _Pragma("unroll")                                                         \
    for (int i = 0; i < 8; i++) {                                             \
        int q = tid + i * NTHREADS;                                           \
        int row = q >> 4, kq = q & 15;                                        \
        av[i] = *(const float4*)(x + (size_t)(m0 + row) * DDIM + (c) * KC + kq * 4); } }
#define STORE_A(buf) {                                                        \
    _Pragma("unroll")                                                         \
    for (int i = 0; i < 8; i++) {                                             \
        int q = tid + i * NTHREADS;                                           \
        int row = q >> 4, kq = q & 15;                                        \
        uint32_t p0a, p1a, p0b, p1b;                                          \
        split2(av[i].x, av[i].y, p0a, p1a);                                   \
        split2(av[i].z, av[i].w, p0b, p1b);                                   \
        char* base = smem + SM_A + (buf) * ABUF + row * RSTRIDE + kq * 8;     \
        *(uint2*)(base + 0 * APL) = make_uint2(p0a, p0b);                     \
        *(uint2*)(base + 1 * APL) = make_uint2(p1a, p1b); } }
    // B: 2 planes x 128 rows x 128B per chunk -> 8 cp.async(16B) per thread
#define LOAD_B(c, buf) {                                                      \
    _Pragma("unroll")                                                         \
    for (int i = 0; i < 8; i++) {                                             \
        int q = tid + i * NTHREADS;                                           \
        int pl = q >> 10, rem = q & 1023, row = rem >> 3, cg = rem & 7;       \
        uint32_t dst = sb + SM_B + (buf) * ABUF + pl * APL + row * RSTRIDE + cg * 16; \
        const __half* src = &g_wp[pl][row][(c) * KC + cg * 8];                \
        CPASYNC16(dst, src); }                                                \
    asm volatile("cp.async.commit_group;" ::: "memory"); }

    // prologue: chunk 0 -> buffer 0
    LOAD_B(0, 0);
    LOAD_A(0);
    STORE_A(0);
    asm volatile("cp.async.wait_group 0;" ::: "memory");
    __syncthreads();

    for (int c = 0; c < NC; c++) {
        const int buf = c & 1;
        if (c + 1 < NC) { LOAD_B(c + 1, buf ^ 1); LOAD_A(c + 1); }

        // ---- compute on current buffer: 4 k16-steps, 3 plane combos ----
#pragma unroll
        for (int ks = 0; ks < 4; ks++) {
            uint32_t a[2][4][4], b[2][4][2];
            const uint32_t abase = sb + SM_A + buf * ABUF + ks * 32;
            const uint32_t bbase = sb + SM_B + buf * ABUF + ks * 32;
#pragma unroll
            for (int pl = 0; pl < 2; pl++)
#pragma unroll
                for (int mt = 0; mt < 4; mt++)
                    LDSM4(a[pl][mt], abase + pl * APL + aoff[mt]);
#pragma unroll
            for (int pl = 0; pl < 2; pl++)
#pragma unroll
                for (int nt = 0; nt < 4; nt++)
                    LDSM2(b[pl][nt], bbase + pl * APL + boff[nt]);

            const int CA[3] = {0, 0, 1};
            const int CB[3] = {0, 1, 0};
#pragma unroll
            for (int q = 0; q < 3; q++)
#pragma unroll
                for (int mt = 0; mt < 4; mt++)
#pragma unroll
                    for (int nt = 0; nt < 4; nt++)
                        MMA16816(acc[mt][nt], a[CA[q]][mt], b[CB[q]][nt]);
        }

        if (c + 1 < NC) STORE_A(buf ^ 1);
        asm volatile("cp.async.wait_group 0;" ::: "memory");
        __syncthreads();
    }

    // ---- stage accumulators to smem (reuses tile region) ----
    float* acc_s = (float*)smem;            // [TM][AS]
    float* su    = acc_s + TM * AS;         // [TM][US]
#pragma unroll
    for (int mt = 0; mt < 4; mt++)
#pragma unroll
        for (int nt = 0; nt < 4; nt++) {
            int r   = wm * 64 + mt * 16 + (lane >> 2);
            int col = wn * 32 + nt * 8 + (lane & 3) * 2;
            acc_s[r * AS + col]           = acc[mt][nt][0];
            acc_s[r * AS + col + 1]       = acc[mt][nt][1];
            acc_s[(r + 8) * AS + col]     = acc[mt][nt][2];
            acc_s[(r + 8) * AS + col + 1] = acc[mt][nt][3];
        }
    // noise_u tile
    {
        const float* ug = u + (size_t)m0 * NEXP;
        for (int q = tid; q < TM * NEXP; q += NTHREADS) {
            int r = q >> 6, cn = q & 63;
            su[r * US + cn] = ug[(size_t)r * NEXP + cn];
        }
    }
    __syncthreads();

    // ---- per-token epilogue: descale, noisy logits, top-2, sparse softmax ----
    if (tid < TM) {
        const int m = m0 + tid;
        float* row = acc_s + tid * AS;
        const float* urow = su + tid * US;

        float v1 = -INFINITY, v2 = -INFINITY;
        int i1 = 0, i2 = 0;
        for (int e = 0; e < NEXP; e++) {
            float lg = row[e] * INVSCALE + rb[e];
            float nz = row[NEXP + e] * INVSCALE + nb[e];
            float sp = fmaxf(nz, 0.f) + log1pf(expf(-fabsf(nz)));
            float nv = lg + sp * urow[e];
            if (nv > v1) { v2 = v1; i2 = i1; v1 = nv; i1 = e; }
            else if (nv > v2) { v2 = nv; i2 = e; }
        }
        float e2 = expf(v2 - v1);
        float den = 1.f + e2;
        float p1 = 1.f / den;
        float p2 = e2 / den;

        for (int e = 0; e < NEXP; e++) row[e] = 0.f;
        row[i1] = p1;
        row[i2] = p2;

        float* oid = out + (size_t)M * NEXP;
        oid[(size_t)m * 2 + 0] = (float)i1;
        oid[(size_t)m * 2 + 1] = (float)i2;
    }
    __syncthreads();

    // coalesced probability writeback
    for (int t = tid; t < TM * (NEXP / 4); t += NTHREADS) {
        int r = t >> 4;
        int c4 = (t & 15) * 4;
        float4 v = make_float4(acc_s[r * AS + c4 + 0],
                               acc_s[r * AS + c4 + 1],
                               acc_s[r * AS + c4 + 2],
                               acc_s[r * AS + c4 + 3]);
        *(float4*)(out + (size_t)(m0 + r) * NEXP + c4) = v;
    }
}

extern "C" void kernel_launch(void* const* d_in, const int* in_sizes, int n_in,
                              void* d_out, int out_size)
{
    const float* x  = (const float*)d_in[0];
    const float* rw = (const float*)d_in[1];
    const float* rb = (const float*)d_in[2];
    const float* nw = (const float*)d_in[3];
    const float* nb = (const float*)d_in[4];
    const float* u  = (const float*)d_in[5];

    const int M = in_sizes[0] / DDIM;  // 16384

    static bool attr_set = false;
    if (!attr_set) {
        cudaFuncSetAttribute(router_hmma_kernel,
                             cudaFuncAttributeMaxDynamicSharedMemorySize,
                             SMEM_BYTES);
        attr_set = true;
    }

    prep_w_kernel<<<(NCOL * DDIM) / 256, 256>>>(rw, nw);
    router_hmma_kernel<<<M / TM, NTHREADS, SMEM_BYTES>>>(x, rb, nb, u, (float*)d_out, M);
}

// round 5
// speedup vs baseline: 2.7551x; 1.0963x over previous
#include <cuda_runtime.h>
#include <cuda_fp16.h>
#include <math.h>
#include <stdint.h>

#define DDIM   2048
#define NEXP   64
#define NCOL   128            // router(64) | noise(64) output columns
#define TM     128            // tokens per CTA
#define KC     64             // K elems per chunk
#define NC     (DDIM / KC)    // 32 chunks
#define NTHREADS 384          // 8 consumer warps + 4 producer warps
#define NPROD  128
#define AS     133
#define US     65
#define WSCALE 2048.0f
#define INVSCALE (1.0f / 2048.0f)

#define RSTRIDE 144                    // smem row stride bytes (128B data + 16B pad)
#define APL     (128 * RSTRIDE)        // 18432 B per plane (128 rows)
#define STAGE_A (2 * APL)              // 36864
#define STAGE_BYTES (2 * STAGE_A)      // 73728 (A planes + B planes)
#define STAGES  3
#define SM_RING 1024
#define SMEM_BYTES (SM_RING + STAGES * STAGE_BYTES)   // 222208

// pre-split W planes, scaled by 2048 (router rows 0..63, noise rows 64..127)
__device__ __half g_wp[2][NCOL][DDIM];

// ---------------- helpers ----------------
__device__ __forceinline__ uint32_t smem_u32(const void* p) {
    uint32_t a;
    asm("{ .reg .u64 t; cvta.to.shared.u64 t, %1; cvt.u32.u64 %0, t; }" : "=r"(a) : "l"(p));
    return a;
}
__device__ __forceinline__ void mbar_init(uint32_t a, uint32_t cnt) {
    asm volatile("mbarrier.init.shared.b64 [%0], %1;" :: "r"(a), "r"(cnt) : "memory");
}
__device__ __forceinline__ void mbar_arrive(uint32_t a) {
    asm volatile("mbarrier.arrive.shared.b64 _, [%0];" :: "r"(a) : "memory");
}
__device__ __forceinline__ void mbar_wait(uint32_t a, uint32_t parity) {
    asm volatile(
        "{\n\t.reg .pred P1;\n\t"
        "W%=:\n\t"
        "mbarrier.try_wait.parity.acquire.cta.shared::cta.b64 P1, [%0], %1, 0x989680;\n\t"
        "@P1 bra.uni D%=;\n\t"
        "bra.uni W%=;\n\t"
        "D%=:\n\t}"
        :: "r"(a), "r"(parity) : "memory");
}
// 2-way fp16 split of a float pair (lo,hi) -> 2 f16x2 regs
__device__ __forceinline__ void split2(float lo, float hi, uint32_t& u0, uint32_t& u1) {
    __half2 h0 = __floats2half2_rn(lo, hi);
    float l0 = __half2float(__low2half(h0));
    float hh = __half2float(__high2half(h0));
    __half2 h1 = __floats2half2_rn(lo - l0, hi - hh);
    u0 = *reinterpret_cast<uint32_t*>(&h0);
    u1 = *reinterpret_cast<uint32_t*>(&h1);
}
#define LDSM4(r, a) \
    asm volatile("ldmatrix.sync.aligned.m8n8.x4.shared.b16 {%0,%1,%2,%3}, [%4];" \
        : "=r"((r)[0]), "=r"((r)[1]), "=r"((r)[2]), "=r"((r)[3]) : "r"(a))
#define MMA16816(d, a, b) \
    asm volatile("mma.sync.aligned.m16n8k16.row.col.f32.f16.f16.f32 " \
        "{%0,%1,%2,%3}, {%4,%5,%6,%7}, {%8,%9}, {%0,%1,%2,%3};" \
        : "+f"((d)[0]), "+f"((d)[1]), "+f"((d)[2]), "+f"((d)[3]) \
        : "r"((a)[0]), "r"((a)[1]), "r"((a)[2]), "r"((a)[3]), "r"((b)[0]), "r"((b)[1]))
#define CPASYNC16(dst, src) \
    asm volatile("cp.async.cg.shared.global [%0], [%1], 16;" :: "r"(dst), "l"(src) : "memory")

// ---------------- prep: split W into 2 scaled fp16 planes ----------------
__global__ void prep_w_kernel(const float* __restrict__ rw, const float* __restrict__ nw) {
    int idx = blockIdx.x * blockDim.x + threadIdx.x;
    int r = idx >> 11, k = idx & 2047;
    float v = WSCALE * ((r < NEXP) ? rw[r * DDIM + k] : nw[(r - NEXP) * DDIM + k]);
    __half b0 = __float2half_rn(v);
    __half b1 = __float2half_rn(v - __half2float(b0));
    g_wp[0][r][k] = b0;
    g_wp[1][r][k] = b1;
}

// ---------------- main fused kernel ----------------
extern __shared__ char smem[];

__global__ __launch_bounds__(NTHREADS, 1)
void router_hmma_kernel(const float* __restrict__ x,
                        const float* __restrict__ rb,
                        const float* __restrict__ nb,
                        const float* __restrict__ u,
                        float* __restrict__ out,
                        int M)
{
    const int tid  = threadIdx.x;
    const int wid  = tid >> 5;
    const int lane = tid & 31;
    const int m0   = blockIdx.x * TM;
    const uint32_t sb = smem_u32(smem);

    // mbarriers: full[s] at s*16, empty[s] at s*16+8
    if (tid == 0) {
#pragma unroll
        for (int s = 0; s < STAGES; s++) {
            mbar_init(sb + s * 16, NPROD);       // full: 128 producer arrivals
            mbar_init(sb + s * 16 + 8, 256);     // empty: 256 consumer arrivals
        }
    }
    __syncthreads();

    if (wid >= 8) {
        // ================= PRODUCER (warps 8-11, 128 threads) =================
        const int ptid = tid - 256;
        float4 av[16];
        for (int c = 0; c < NC; c++) {
            const int s = c % STAGES;
            const uint32_t aA = sb + SM_RING + s * STAGE_BYTES;
            const uint32_t aB = aA + STAGE_A;
            mbar_wait(sb + s * 16 + 8, ((c / STAGES) & 1) ^ 1);   // wait empty

            // B: 2 planes x 128 rows x 8 16B-cells = 2048 cells, 16/thread
#pragma unroll
            for (int i = 0; i < 16; i++) {
                int q = ptid + i * NPROD;
                int pl = q >> 10, rem = q & 1023, row = rem >> 3, cg = rem & 7;
                uint32_t dst = aB + pl * APL + row * RSTRIDE + cg * 16;
                CPASYNC16(dst, &g_wp[pl][row][c * KC + cg * 8]);
            }
            asm volatile("cp.async.commit_group;" ::: "memory");

            // A: 128 rows x 16 float4 = 2048, 16/thread
#pragma unroll
            for (int i = 0; i < 16; i++) {
                int q = ptid + i * NPROD;
                int row = q >> 4, kq = q & 15;
                av[i] = *(const float4*)(x + (size_t)(m0 + row) * DDIM + c * KC + kq * 4);
            }
#pragma unroll
            for (int i = 0; i < 16; i++) {
                int q = ptid + i * NPROD;
                int row = q >> 4, kq = q & 15;
                uint32_t p0a, p1a, p0b, p1b;
                split2(av[i].x, av[i].y, p0a, p1a);
                split2(av[i].z, av[i].w, p0b, p1b);
                uint32_t base = aA + row * RSTRIDE + kq * 8;
                *(uint2*)(smem + (base - sb) + 0 * APL) = make_uint2(p0a, p0b);
                *(uint2*)(smem + (base - sb) + 1 * APL) = make_uint2(p1a, p1b);
            }
            asm volatile("cp.async.wait_group 0;" ::: "memory");
            mbar_arrive(sb + s * 16);                              // full
        }
    } else {
        // ================= CONSUMER (warps 0-7, 256 threads) =================
        const int wm = wid >> 2;   // 0..1 -> 64-row slab
        const int wn = wid & 3;    // 0..3 -> 32-col slab

        uint32_t aoff[4], boff[2];
#pragma unroll
        for (int mt = 0; mt < 4; mt++) {
            int row = wm * 64 + mt * 16 + (lane & 7) + 8 * ((lane >> 3) & 1);
            aoff[mt] = (uint32_t)(row * RSTRIDE + 16 * ((lane >> 4) & 1));
        }
#pragma unroll
        for (int ntp = 0; ntp < 2; ntp++) {
            int row = wn * 32 + ntp * 16 + ((lane >> 4) & 1) * 8 + (lane & 7);
            boff[ntp] = (uint32_t)(row * RSTRIDE + 16 * ((lane >> 3) & 1));
        }

        float acc[4][4][4];
#pragma unroll
        for (int mt = 0; mt < 4; mt++)
#pragma unroll
            for (int nt = 0; nt < 4; nt++)
#pragma unroll
                for (int e = 0; e < 4; e++) acc[mt][nt][e] = 0.f;

        for (int c = 0; c < NC; c++) {
            const int s = c % STAGES;
            const uint32_t aA = sb + SM_RING + s * STAGE_BYTES;
            const uint32_t aB = aA + STAGE_A;
            mbar_wait(sb + s * 16, (c / STAGES) & 1);              // wait full

#pragma unroll
            for (int ks = 0; ks < 4; ks++) {
                uint32_t a[2][4][4], b[2][4][2];
#pragma unroll
                for (int pl = 0; pl < 2; pl++)
#pragma unroll
                    for (int mt = 0; mt < 4; mt++)
                        LDSM4(a[pl][mt], aA + pl * APL + ks * 32 + aoff[mt]);
#pragma unroll
                for (int pl = 0; pl < 2; pl++)
#pragma unroll
                    for (int ntp = 0; ntp < 2; ntp++) {
                        uint32_t t4[4];
                        LDSM4(t4, aB + pl * APL + ks * 32 + boff[ntp]);
                        b[pl][2 * ntp][0]     = t4[0];
                        b[pl][2 * ntp][1]     = t4[1];
                        b[pl][2 * ntp + 1][0] = t4[2];
                        b[pl][2 * ntp + 1][1] = t4[3];
                    }
                const int CA[3] = {0, 0, 1};
                const int CB[3] = {0, 1, 0};
#pragma unroll
                for (int q = 0; q < 3; q++)
#pragma unroll
                    for (int mt = 0; mt < 4; mt++)
#pragma unroll
                        for (int nt = 0; nt < 4; nt++)
                            MMA16816(acc[mt][nt], a[CA[q]][mt], b[CB[q]][nt]);
            }
            mbar_arrive(sb + s * 16 + 8);                          // arrive empty
        }

        // stash acc in registers; staging happens after the block-wide sync below
        __syncthreads();   // (consumers + producers) — ring dead, safe to reuse
        float* acc_s = (float*)(smem + SM_RING);
#pragma unroll
        for (int mt = 0; mt < 4; mt++)
#pragma unroll
            for (int nt = 0; nt < 4; nt++) {
                int r   = wm * 64 + mt * 16 + (lane >> 2);
                int col = wn * 32 + nt * 8 + (lane & 3) * 2;
                acc_s[r * AS + col]           = acc[mt][nt][0];
                acc_s[r * AS + col + 1]       = acc[mt][nt][1];
                acc_s[(r + 8) * AS + col]     = acc[mt][nt][2];
                acc_s[(r + 8) * AS + col + 1] = acc[mt][nt][3];
            }
    }
    if (wid >= 8) __syncthreads();   // producers join the same barrier

    // ---- noise_u tile (all 384 threads) ----
    float* acc_s = (float*)(smem + SM_RING);
    float* su    = acc_s + TM * AS;
    {
        const float* ug = u + (size_t)m0 * NEXP;
        for (int q = tid; q < TM * NEXP; q += NTHREADS) {
            int r = q >> 6, cn = q & 63;
            su[r * US + cn] = ug[(size_t)r * NEXP + cn];
        }
    }
    __syncthreads();

    // ---- per-token epilogue ----
    if (tid < TM) {
        const int m = m0 + tid;
        float* row = acc_s + tid * AS;
        const float* urow = su + tid * US;

        float v1 = -INFINITY, v2 = -INFINITY;
        int i1 = 0, i2 = 0;
        for (int e = 0; e < NEXP; e++) {
            float lg = row[e] * INVSCALE + rb[e];
            float nz = row[NEXP + e] * INVSCALE + nb[e];
            float sp = fmaxf(nz, 0.f) + log1pf(expf(-fabsf(nz)));
            float nv = lg + sp * urow[e];
            if (nv > v1) { v2 = v1; i2 = i1; v1 = nv; i1 = e; }
            else if (nv > v2) { v2 = nv; i2 = e; }
        }
        float e2 = expf(v2 - v1);
        float den = 1.f + e2;
        float p1 = 1.f / den;
        float p2 = e2 / den;

        for (int e = 0; e < NEXP; e++) row[e] = 0.f;
        row[i1] = p1;
        row[i2] = p2;

        float* oid = out + (size_t)M * NEXP;
        oid[(size_t)m * 2 + 0] = (float)i1;
        oid[(size_t)m * 2 + 1] = (float)i2;
    }
    __syncthreads();

    // coalesced probability writeback
    for (int t = tid; t < TM * (NEXP / 4); t += NTHREADS) {
        int r = t >> 4;
        int c4 = (t & 15) * 4;
        float4 v = make_float4(acc_s[r * AS + c4 + 0],
                               acc_s[r * AS + c4 + 1],
                               acc_s[r * AS + c4 + 2],
                               acc_s[r * AS + c4 + 3]);
        *(float4*)(out + (size_t)(m0 + r) * NEXP + c4) = v;
    }
}

extern "C" void kernel_launch(void* const* d_in, const int* in_sizes, int n_in,
                              void* d_out, int out_size)
{
    const float* x  = (const float*)d_in[0];
    const float* rw = (const float*)d_in[1];
    const float* rb = (const float*)d_in[2];
    const float* nw = (const float*)d_in[3];
    const float* nb = (const float*)d_in[4];
    const float* u  = (const float*)d_in[5];

    const int M = in_sizes[0] / DDIM;  // 16384

    static bool attr_set = false;
    if (!attr_set) {
        cudaFuncSetAttribute(router_hmma_kernel,
                             cudaFuncAttributeMaxDynamicSharedMemorySize,
                             SMEM_BYTES);
        attr_set = true;
    }

    prep_w_kernel<<<(NCOL * DDIM) / 256, 256>>>(rw, nw);
    router_hmma_kernel<<<M / TM, NTHREADS, SMEM_BYTES>>>(x, rb, nb, u, (float*)d_out, M);
}